// round 1
// baseline (speedup 1.0000x reference)
#include <cuda_runtime.h>

#define Bn 64
#define Hn 128
#define Cn 1024
#define Qn 128
#define NT 8           // number of 128-row c tiles (Cn/128)

// ---------------- scratch (device globals; no allocation) ----------------
__device__ float g_S[Bn * Cn * Qn];        // raw scores S (33.5 MB)
__device__ float g_cT[Bn * Cn * Hn];       // c transposed: (B, C, H)
__device__ float g_qT[Bn * Qn * Hn];       // q transposed: (B, Q, H)
__device__ float g_rowM[Bn * Cn];
__device__ float g_rowZ[Bn * Cn];
__device__ float g_pM[Bn * NT * Qn];       // per-tile column max partials
__device__ float g_pZ[Bn * NT * Qn];       // per-tile column sumexp partials
__device__ float g_colM[Bn * Qn];
__device__ float g_colZ[Bn * Qn];
__device__ float g_qbp[Bn * NT * Qn * Hn]; // split-K partials of qb
__device__ float g_qb[Bn * Qn * Hn];       // qb = b_att^T @ c^T, normalized

// ---------------- K0: transposes (B,H,L) -> (B,L,H) ----------------
__global__ void ktrans_c(const float* __restrict__ in) {
    __shared__ float t[32][33];
    int b = blockIdx.z;
    int l0 = blockIdx.x * 32, h0 = blockIdx.y * 32;
    int tx = threadIdx.x, ty = threadIdx.y;
#pragma unroll
    for (int i = 0; i < 32; i += 8)
        t[ty + i][tx] = in[((size_t)b * Hn + h0 + ty + i) * Cn + l0 + tx];
    __syncthreads();
#pragma unroll
    for (int i = 0; i < 32; i += 8)
        g_cT[((size_t)b * Cn + l0 + ty + i) * Hn + h0 + tx] = t[tx][ty + i];
}

__global__ void ktrans_q(const float* __restrict__ in) {
    __shared__ float t[32][33];
    int b = blockIdx.z;
    int l0 = blockIdx.x * 32, h0 = blockIdx.y * 32;
    int tx = threadIdx.x, ty = threadIdx.y;
#pragma unroll
    for (int i = 0; i < 32; i += 8)
        t[ty + i][tx] = in[((size_t)b * Hn + h0 + ty + i) * Qn + l0 + tx];
    __syncthreads();
#pragma unroll
    for (int i = 0; i < 32; i += 8)
        g_qT[((size_t)b * Qn + l0 + ty + i) * Hn + h0 + tx] = t[tx][ty + i];
}

// ---------------- K1: scores S + row stats + column partial stats --------
// grid(NT, Bn), block 256. smem: As(16384) Bs(16384) s0s s1s qms cms pmc (5*128) red(2048)
#define K1_SMEM ((16384 * 2 + 5 * 128 + 2048) * 4)

__global__ __launch_bounds__(256, 1) void k1_score(
    const float* __restrict__ c_g, const float* __restrict__ q_g,
    const float* __restrict__ cmask, const float* __restrict__ qmask,
    const float* __restrict__ wc, const float* __restrict__ wq,
    const float* __restrict__ wcq, const float* __restrict__ bias)
{
    extern __shared__ float sm[];
    float* As  = sm;             // [h][cc], c tile (later scaled by wcq)
    float* Bs  = As + 16384;     // [h][q],  q tile
    float* s0s = Bs + 16384;
    float* s1s = s0s + 128;
    float* qms = s1s + 128;
    float* cms = qms + 128;
    float* pmc = cms + 128;
    float* red = pmc + 128;      // 16*128

    int b = blockIdx.y, ct = blockIdx.x, c0 = ct * 128;
    int tid = threadIdx.x, tx = tid & 15, ty = tid >> 4;

    for (int i = tid; i < 16384; i += 256) {
        int h = i >> 7, x = i & 127;
        As[i] = c_g[((size_t)b * Hn + h) * Cn + c0 + x];
        Bs[i] = q_g[((size_t)b * Hn + h) * Qn + x];
    }
    if (tid < 128) { qms[tid] = qmask[b * Qn + tid]; cms[tid] = cmask[b * Cn + c0 + tid]; }
    __syncthreads();

    if (tid < 128) {
        float a = 0.f;
#pragma unroll 8
        for (int h = 0; h < 128; h++) a += As[h * 128 + tid] * wc[h];
        s0s[tid] = a;
    } else {
        int qq = tid - 128; float a = 0.f;
#pragma unroll 8
        for (int h = 0; h < 128; h++) a += Bs[h * 128 + qq] * wq[h];
        s1s[qq] = a;
    }
    __syncthreads();
    for (int i = tid; i < 16384; i += 256) As[i] *= wcq[i >> 7];
    __syncthreads();

    float acc[8][8];
#pragma unroll
    for (int i = 0; i < 8; i++)
#pragma unroll
        for (int j = 0; j < 8; j++) acc[i][j] = 0.f;

#pragma unroll 4
    for (int k = 0; k < 128; k++) {
        float4 a0 = *(const float4*)&As[k * 128 + ty * 8];
        float4 a1 = *(const float4*)&As[k * 128 + ty * 8 + 4];
        float4 b0 = *(const float4*)&Bs[k * 128 + tx * 8];
        float4 b1 = *(const float4*)&Bs[k * 128 + tx * 8 + 4];
        float af[8] = {a0.x, a0.y, a0.z, a0.w, a1.x, a1.y, a1.z, a1.w};
        float bf[8] = {b0.x, b0.y, b0.z, b0.w, b1.x, b1.y, b1.z, b1.w};
#pragma unroll
        for (int i = 0; i < 8; i++)
#pragma unroll
            for (int j = 0; j < 8; j++) acc[i][j] += af[i] * bf[j];
    }

    float bs0 = bias[0];
#pragma unroll
    for (int i = 0; i < 8; i++) {
        float s0v = s0s[ty * 8 + i];
#pragma unroll
        for (int j = 0; j < 8; j++) acc[i][j] += s0v + s1s[tx * 8 + j] + bs0;
    }

    // write raw S
#pragma unroll
    for (int i = 0; i < 8; i++) {
        size_t off = ((size_t)b * Cn + c0 + ty * 8 + i) * Qn + tx * 8;
        *(float4*)&g_S[off]     = make_float4(acc[i][0], acc[i][1], acc[i][2], acc[i][3]);
        *(float4*)&g_S[off + 4] = make_float4(acc[i][4], acc[i][5], acc[i][6], acc[i][7]);
    }

    // row stats (softmax over q, masked by q_mask)
    float qmv[8];
#pragma unroll
    for (int j = 0; j < 8; j++) qmv[j] = qms[tx * 8 + j];
#pragma unroll
    for (int i = 0; i < 8; i++) {
        float m = -1e30f;
#pragma unroll
        for (int j = 0; j < 8; j++) {
            float rv = (qmv[j] > 0.f) ? acc[i][j] : -1e30f;
            m = fmaxf(m, rv);
        }
#pragma unroll
        for (int off = 8; off >= 1; off >>= 1)
            m = fmaxf(m, __shfl_xor_sync(0xffffffffu, m, off));
        float z = 0.f;
#pragma unroll
        for (int j = 0; j < 8; j++)
            z += (qmv[j] > 0.f) ? __expf(acc[i][j] - m) : 0.f;
#pragma unroll
        for (int off = 8; off >= 1; off >>= 1)
            z += __shfl_xor_sync(0xffffffffu, z, off);
        if (tx == 0) {
            g_rowM[b * Cn + c0 + ty * 8 + i] = m;
            g_rowZ[b * Cn + c0 + ty * 8 + i] = z;
        }
    }

    // column partial stats (softmax over c, masked by c_mask)
    float cmv[8];
#pragma unroll
    for (int i = 0; i < 8; i++) cmv[i] = cms[ty * 8 + i];
#pragma unroll
    for (int j = 0; j < 8; j++) {
        float cm = -1e30f;
#pragma unroll
        for (int i = 0; i < 8; i++) {
            float cv = (cmv[i] > 0.f) ? acc[i][j] : -1e30f;
            cm = fmaxf(cm, cv);
        }
        red[ty * 128 + tx * 8 + j] = cm;
    }
    __syncthreads();
    if (tid < 128) {
        float pm = -1e30f;
#pragma unroll
        for (int t = 0; t < 16; t++) pm = fmaxf(pm, red[t * 128 + tid]);
        pmc[tid] = pm;
    }
    __syncthreads();
#pragma unroll
    for (int j = 0; j < 8; j++) {
        float pm = pmc[tx * 8 + j];
        float cz = 0.f;
#pragma unroll
        for (int i = 0; i < 8; i++)
            cz += (cmv[i] > 0.f) ? __expf(acc[i][j] - pm) : 0.f;
        red[ty * 128 + tx * 8 + j] = cz;
    }
    __syncthreads();
    if (tid < 128) {
        float z = 0.f;
#pragma unroll
        for (int t = 0; t < 16; t++) z += red[t * 128 + tid];
        g_pM[(b * NT + ct) * Qn + tid] = pmc[tid];
        g_pZ[(b * NT + ct) * Qn + tid] = z;
    }
}

// ---------------- K2: combine column partial stats ----------------
__global__ void k2_colstats() {
    int b = blockIdx.x, q = threadIdx.x;
    float m = -3.4e38f;
#pragma unroll
    for (int t = 0; t < NT; t++) m = fmaxf(m, g_pM[(b * NT + t) * Qn + q]);
    float z = 0.f;
#pragma unroll
    for (int t = 0; t < NT; t++)
        z += g_pZ[(b * NT + t) * Qn + q] * __expf(g_pM[(b * NT + t) * Qn + q] - m);
    g_colM[b * Qn + q] = m;
    g_colZ[b * Qn + q] = z;
}

// ---------------- K3: split-K partials of qb = b_att^T @ c^T ----------------
// grid(NT, Bn), block 256. smem: Es(16384) Cs(16384) cMs(128) cms(128)
#define K3_SMEM ((16384 * 2 + 256) * 4)

__global__ __launch_bounds__(256, 1) void k3_qbp(const float* __restrict__ cmask)
{
    extern __shared__ float sm[];
    float* Es  = sm;             // [k=c][q]  un-normalized exp
    float* Cs  = Es + 16384;     // [k=c][h]
    float* cMs = Cs + 16384;
    float* cms = cMs + 128;

    int b = blockIdx.y, ct = blockIdx.x, c0 = ct * 128;
    int tid = threadIdx.x, tx = tid & 15, ty = tid >> 4;

    if (tid < 128) { cMs[tid] = g_colM[b * Qn + tid]; cms[tid] = cmask[b * Cn + c0 + tid]; }
    __syncthreads();

    for (int i = tid; i < 16384; i += 256) {
        int k = i >> 7, x = i & 127;
        float s = g_S[((size_t)b * Cn + c0 + k) * Qn + x];
        Es[i] = (cms[k] > 0.f) ? __expf(s - cMs[x]) : 0.f;
        Cs[i] = g_cT[((size_t)b * Cn + c0 + k) * Hn + x];
    }
    __syncthreads();

    float acc[8][8];
#pragma unroll
    for (int i = 0; i < 8; i++)
#pragma unroll
        for (int j = 0; j < 8; j++) acc[i][j] = 0.f;

#pragma unroll 4
    for (int k = 0; k < 128; k++) {
        float4 a0 = *(const float4*)&Es[k * 128 + ty * 8];
        float4 a1 = *(const float4*)&Es[k * 128 + ty * 8 + 4];
        float4 b0 = *(const float4*)&Cs[k * 128 + tx * 8];
        float4 b1 = *(const float4*)&Cs[k * 128 + tx * 8 + 4];
        float af[8] = {a0.x, a0.y, a0.z, a0.w, a1.x, a1.y, a1.z, a1.w};
        float bf[8] = {b0.x, b0.y, b0.z, b0.w, b1.x, b1.y, b1.z, b1.w};
#pragma unroll
        for (int i = 0; i < 8; i++)
#pragma unroll
            for (int j = 0; j < 8; j++) acc[i][j] += af[i] * bf[j];
    }

#pragma unroll
    for (int i = 0; i < 8; i++) {
        size_t off = ((size_t)(b * NT + ct) * Qn + ty * 8 + i) * Hn + tx * 8;
        *(float4*)&g_qbp[off]     = make_float4(acc[i][0], acc[i][1], acc[i][2], acc[i][3]);
        *(float4*)&g_qbp[off + 4] = make_float4(acc[i][4], acc[i][5], acc[i][6], acc[i][7]);
    }
}

// ---------------- K3b: combine split-K partials, normalize by colZ ----------
__global__ void k3b_combine() {
    int idx = blockIdx.x * 256 + threadIdx.x;   // < Bn*Qn*Hn
    int b = idx >> 14;
    int rem = idx & 16383;
    int q = rem >> 7;
    float s = 0.f;
#pragma unroll
    for (int t = 0; t < NT; t++) s += g_qbp[(size_t)(b * NT + t) * 16384 + rem];
    float z = g_colZ[b * Qn + q];
    g_qb[idx] = (z > 0.f) ? s / z : 0.f;
}

// ---------------- K4: a = A@q^T, bb = A@qb, assemble output ----------------
// grid(NT, Bn), block 256. smem: Es(16384, xor-swizzled) Qs(16384) QBs(16384) rms(128) qms(128)
#define K4_SMEM ((16384 * 3 + 256) * 4)

__global__ __launch_bounds__(256, 1) void k4_out(
    const float* __restrict__ c_g, const float* __restrict__ qmask,
    float* __restrict__ out)
{
    extern __shared__ float sm[];
    float* Es  = sm;             // swizzled: E[q][cr] at q*128 + ((cr^q)&127)
    float* Qs  = Es + 16384;     // [q][h]
    float* QBs = Qs + 16384;     // [q][h]
    float* rms = QBs + 16384;
    float* qms = rms + 128;

    int b = blockIdx.y, ct = blockIdx.x, c0 = ct * 128;
    int tid = threadIdx.x, tx = tid & 15, ty = tid >> 4;

    if (tid < 128) { rms[tid] = g_rowM[b * Cn + c0 + tid]; qms[tid] = qmask[b * Qn + tid]; }
    __syncthreads();

    for (int i = tid; i < 16384; i += 256) {
        int r = i >> 7, x = i & 127;
        float s = g_S[((size_t)b * Cn + c0 + r) * Qn + x];
        float e = (qms[x] > 0.f) ? __expf(s - rms[r]) : 0.f;
        Es[x * 128 + ((r ^ x) & 127)] = e;
        Qs[i]  = g_qT[((size_t)b * Qn + r) * Hn + x];
        QBs[i] = g_qb[((size_t)b * Qn + r) * Hn + x];
    }
    __syncthreads();

    float aa[8][8], ab[8][8];
#pragma unroll
    for (int i = 0; i < 8; i++)
#pragma unroll
        for (int j = 0; j < 8; j++) { aa[i][j] = 0.f; ab[i][j] = 0.f; }

    int cr0 = ty * 8;
#pragma unroll 2
    for (int k = 0; k < 128; k++) {
        float af[8];
#pragma unroll
        for (int i = 0; i < 8; i++)
            af[i] = Es[k * 128 + (((cr0 + i) ^ k) & 127)];
        float4 q0 = *(const float4*)&Qs[k * 128 + tx * 8];
        float4 q1 = *(const float4*)&Qs[k * 128 + tx * 8 + 4];
        float4 p0 = *(const float4*)&QBs[k * 128 + tx * 8];
        float4 p1 = *(const float4*)&QBs[k * 128 + tx * 8 + 4];
        float bq[8] = {q0.x, q0.y, q0.z, q0.w, q1.x, q1.y, q1.z, q1.w};
        float bp[8] = {p0.x, p0.y, p0.z, p0.w, p1.x, p1.y, p1.z, p1.w};
#pragma unroll
        for (int i = 0; i < 8; i++)
#pragma unroll
            for (int j = 0; j < 8; j++) {
                aa[i][j] += af[i] * bq[j];
                ab[i][j] += af[i] * bp[j];
            }
    }

    float rz[8];
#pragma unroll
    for (int i = 0; i < 8; i++) {
        float z = g_rowZ[b * Cn + c0 + cr0 + i];
        rz[i] = (z > 0.f) ? 1.f / z : 0.f;
    }

    __syncthreads();   // done reading Qs/QBs; reuse as staging
    float* StA = Qs;
    float* StB = QBs;
#pragma unroll
    for (int i = 0; i < 8; i++) {
        int cr = cr0 + i;
#pragma unroll
        for (int j = 0; j < 8; j++) {
            int h = tx * 8 + j;
            StA[cr * 128 + ((h ^ cr) & 127)] = aa[i][j] * rz[i];
            StB[cr * 128 + ((h ^ cr) & 127)] = ab[i][j] * rz[i];
        }
    }
    __syncthreads();

    const size_t HC = (size_t)Hn * Cn;
    for (int i = tid; i < 16384; i += 256) {
        int h = i >> 7, cc = i & 127;
        float a  = StA[cc * 128 + ((h ^ cc) & 127)];
        float bb = StB[cc * 128 + ((h ^ cc) & 127)];
        float cv = c_g[((size_t)b * Hn + h) * Cn + c0 + cc];
        size_t o = (size_t)b * 4 * HC + (size_t)h * Cn + c0 + cc;
        out[o]          = cv;
        out[o + HC]     = a;
        out[o + 2 * HC] = cv * a;
        out[o + 3 * HC] = cv * bb;
    }
}

// ---------------- launch ----------------
extern "C" void kernel_launch(void* const* d_in, const int* in_sizes, int n_in,
                              void* d_out, int out_size)
{
    const float* c     = (const float*)d_in[0];
    const float* q     = (const float*)d_in[1];
    const float* cmask = (const float*)d_in[2];
    const float* qmask = (const float*)d_in[3];
    const float* wc    = (const float*)d_in[4];
    const float* wq    = (const float*)d_in[5];
    const float* wcq   = (const float*)d_in[6];
    const float* bias  = (const float*)d_in[7];
    float* out = (float*)d_out;

    cudaFuncSetAttribute(k1_score, cudaFuncAttributeMaxDynamicSharedMemorySize, K1_SMEM);
    cudaFuncSetAttribute(k3_qbp,   cudaFuncAttributeMaxDynamicSharedMemorySize, K3_SMEM);
    cudaFuncSetAttribute(k4_out,   cudaFuncAttributeMaxDynamicSharedMemorySize, K4_SMEM);

    ktrans_c<<<dim3(Cn / 32, Hn / 32, Bn), dim3(32, 8)>>>(c);
    ktrans_q<<<dim3(Qn / 32, Hn / 32, Bn), dim3(32, 8)>>>(q);
    k1_score<<<dim3(NT, Bn), 256, K1_SMEM>>>(c, q, cmask, qmask, wc, wq, wcq, bias);
    k2_colstats<<<Bn, Qn>>>();
    k3_qbp<<<dim3(NT, Bn), 256, K3_SMEM>>>(cmask);
    k3b_combine<<<(Bn * Qn * Hn) / 256, 256>>>();
    k4_out<<<dim3(NT, Bn), 256, K4_SMEM>>>(c, qmask, out);
}